// round 6
// baseline (speedup 1.0000x reference)
#include <cuda_runtime.h>
#include <cuda_fp16.h>
#include <math.h>
#include <stdint.h>

#define B_SZ 2048
#define HDIM 1024
#define DDIM 512
#define MAXN 64
#define MID_SP 512
#define MID_CD 512
#define MID_DEC 768
#define NROWS (B_SZ * MAXN)

__device__ int    g_n[B_SZ];
__device__ int    g_off[B_SZ];
__device__ int    g_vpad;
__device__ int    g_rowmap[NROWS];
__device__ float  g_enc[65 * HDIM];
__device__ float  g_zc[B_SZ * HDIM];
__device__ __half g_W1Th[MID_DEC * HDIM];
__device__ __half g_W2Th[DDIM * MID_DEC];
__device__ __half g_Th[(size_t)NROWS * MID_DEC];

__device__ __forceinline__ float mishf(float x) {
    float sp = log1pf(expf(x));
    if (x > 20.f) sp = x;
    return x * tanhf(sp);
}
// FMA-only mish (no MUFU)
__device__ __forceinline__ float mish_poly(float x) {
    float xc = fminf(fmaxf(x, -30.f), 20.f);
    float t = xc * 1.44269504089f;
    float fn = rintf(t);
    float g = (t - fn) * 0.69314718056f;
    float p = 1.f / 720.f;
    p = fmaf(p, g, 1.f / 120.f);
    p = fmaf(p, g, 1.f / 24.f);
    p = fmaf(p, g, 1.f / 6.f);
    p = fmaf(p, g, 0.5f);
    p = fmaf(p, g, 1.f);
    p = fmaf(p, g, 1.f);
    float ex = p * __uint_as_float(((unsigned)((int)fn + 127)) << 23);
    float u = 1.f + ex;
    float d = fmaf(u, u, 1.f);
    float r = __uint_as_float(0x7EF311C3u - __float_as_uint(d));
    r = r * (2.f - d * r);
    r = r * (2.f - d * r);
    r = r * (2.f - d * r);
    float m = x * (fmaf(u, u, -1.f) * r);
    return (x > 20.f) ? x : m;
}
__device__ __forceinline__ void mma_f16(float* d, const uint32_t* a, const uint32_t* b) {
    asm volatile(
        "mma.sync.aligned.m16n8k16.row.col.f32.f16.f16.f32 "
        "{%0,%1,%2,%3}, {%4,%5,%6,%7}, {%8,%9}, {%0,%1,%2,%3};"
        : "+f"(d[0]), "+f"(d[1]), "+f"(d[2]), "+f"(d[3])
        : "r"(a[0]), "r"(a[1]), "r"(a[2]), "r"(a[3]), "r"(b[0]), "r"(b[1]));
}
__device__ __forceinline__ void ldsm4(uint32_t* r, uint32_t addr) {
    asm volatile("ldmatrix.sync.aligned.m8n8.x4.shared.b16 {%0,%1,%2,%3}, [%4];"
                 : "=r"(r[0]), "=r"(r[1]), "=r"(r[2]), "=r"(r[3]) : "r"(addr));
}
#define CPASYNC16(dst, src) \
    asm volatile("cp.async.cg.shared.global [%0], [%1], 16;" :: "r"(dst), "l"(src))
#define CPCOMMIT() asm volatile("cp.async.commit_group;" ::: "memory")
#define CPWAIT0()  asm volatile("cp.async.wait_group 0;" ::: "memory")
#define CPWAIT1()  asm volatile("cp.async.wait_group 1;" ::: "memory")

__device__ __forceinline__ uint32_t smem_u32(const void* p) {
    uint32_t a;
    asm("{ .reg .u64 t; cvta.to.shared.u64 t, %1; cvt.u32.u64 %0, t; }" : "=r"(a) : "l"(p));
    return a;
}
__device__ __forceinline__ uint32_t h2u(__half2 h) { return *(uint32_t*)&h; }

// ---------------- size_pred: 16 rows/CTA, shuffle reductions (fp32) ----------------
__global__ __launch_bounds__(256)
void size_pred_kernel(const float* __restrict__ z, const float* __restrict__ w1,
                      const float* __restrict__ b1v, const float* __restrict__ g,
                      const float* __restrict__ beta, const float* __restrict__ w2,
                      const float* __restrict__ b2v)
{
    extern __shared__ float sps[];
    float* z_s  = sps;                 // 16*1024
    float* wred = sps + 16 * HDIM;     // 16
    float* mu_s = wred + 16;           // 16
    float* rs_s = mu_s + 16;           // 16
    const int tid = threadIdx.x, lane = tid & 31, wid = tid >> 5;
    const int b0 = blockIdx.x * 16;

    for (int i = tid; i < 16 * HDIM; i += 256)
        z_s[i] = z[(size_t)b0 * HDIM + i];
    __syncthreads();

    float pre[16][2];
#pragma unroll
    for (int r = 0; r < 16; r++) { pre[r][0] = 0.f; pre[r][1] = 0.f; }
    for (int k = 0; k < HDIM; k++) {
        float wa = w1[k * MID_SP + tid], wb = w1[k * MID_SP + tid + 256];
#pragma unroll
        for (int r = 0; r < 16; r++) {
            float zv = z_s[r * HDIM + k];
            pre[r][0] = fmaf(zv, wa, pre[r][0]);
            pre[r][1] = fmaf(zv, wb, pre[r][1]);
        }
    }
    float ba = b1v[tid], bb = b1v[tid + 256];
#pragma unroll
    for (int r = 0; r < 16; r++) { pre[r][0] += ba; pre[r][1] += bb; }

    for (int r = 0; r < 16; r++) {
        float v = pre[r][0] + pre[r][1];
        float q = pre[r][0] * pre[r][0] + pre[r][1] * pre[r][1];
#pragma unroll
        for (int s = 16; s > 0; s >>= 1) {
            v += __shfl_xor_sync(0xFFFFFFFFu, v, s);
            q += __shfl_xor_sync(0xFFFFFFFFu, q, s);
        }
        if (lane == 0) { wred[wid] = v; wred[8 + wid] = q; }
        __syncthreads();
        if (tid == 0) {
            float sv = 0.f, sq = 0.f;
            for (int w = 0; w < 8; w++) { sv += wred[w]; sq += wred[8 + w]; }
            float mu = sv * (1.f / 512.f);
            mu_s[r] = mu;
            rs_s[r] = rsqrtf(sq * (1.f / 512.f) - mu * mu + 1e-5f);
        }
        __syncthreads();
    }

    float ga = g[tid], gb = g[tid + 256], bta = beta[tid], btb = beta[tid + 256];
    float w2a = w2[tid], w2b = w2[tid + 256];
    for (int r = 0; r < 16; r++) {
        float h0 = mishf((pre[r][0] - mu_s[r]) * rs_s[r] * ga + bta);
        float h1 = mishf((pre[r][1] - mu_s[r]) * rs_s[r] * gb + btb);
        float v = h0 * w2a + h1 * w2b;
#pragma unroll
        for (int s = 16; s > 0; s >>= 1)
            v += __shfl_xor_sync(0xFFFFFFFFu, v, s);
        if (lane == 0) wred[wid] = v;
        __syncthreads();
        if (tid == 0) {
            float sv = 0.f;
            for (int w = 0; w < 8; w++) sv += wred[w];
            int n = (int)rintf(sv + b2v[0]);
            g_n[b0 + r] = min(max(n, 0), MAXN);
        }
        __syncthreads();
    }
}

// ---------------- cardinality table ----------------
__global__ __launch_bounds__(256)
void enc_kernel(const float* __restrict__ cw1, const float* __restrict__ cb1,
                const float* __restrict__ cw2, const float* __restrict__ cb2)
{
    __shared__ float m_s[MID_CD];
    const int v = blockIdx.x, tid = threadIdx.x;
    for (int j = tid; j < MID_CD; j += 256)
        m_s[j] = mishf((float)v * cw1[j] + cb1[j]);
    __syncthreads();
    for (int j = tid; j < HDIM; j += 256) {
        float acc = cb2[j];
        for (int m = 0; m < MID_CD; m++)
            acc = fmaf(m_s[m], cw2[m * HDIM + j], acc);
        g_enc[v * HDIM + j] = acc;
    }
}

__global__ __launch_bounds__(256)
void zc_kernel(const float* __restrict__ z)
{
    int idx = blockIdx.x * 256 + threadIdx.x;
    int b = idx >> 10, i = idx & 1023;
    g_zc[idx] = z[idx] - g_enc[g_n[b] * HDIM + i];
}

__global__ void transpose_h(const float* __restrict__ src, int R, int C, int which)
{
    __shared__ float t[32][33];
    __half* dst = which ? g_W2Th : g_W1Th;
    int c0 = blockIdx.x * 32, r0 = blockIdx.y * 32;
#pragma unroll
    for (int i = 0; i < 32; i += 8)
        t[threadIdx.y + i][threadIdx.x] = src[(size_t)(r0 + threadIdx.y + i) * C + c0 + threadIdx.x];
    __syncthreads();
#pragma unroll
    for (int i = 0; i < 32; i += 8)
        dst[(size_t)(c0 + threadIdx.y + i) * R + r0 + threadIdx.x] = __float2half(t[threadIdx.x][threadIdx.y + i]);
}

__global__ __launch_bounds__(1024)
void scan_kernel()
{
    __shared__ int s[2048];
    int t = threadIdx.x;
    s[t] = g_n[t]; s[t + 1024] = g_n[t + 1024];
    __syncthreads();
    for (int off = 1; off < 2048; off <<= 1) {
        int a = (t >= off) ? s[t - off] : 0;
        int b = s[t + 1024 - off];
        __syncthreads();
        s[t] += a; s[t + 1024] += b;
        __syncthreads();
    }
    g_off[t] = s[t] - g_n[t];
    g_off[t + 1024] = s[t + 1024] - g_n[t + 1024];
    if (t == 1023) g_vpad = (s[2047] + 127) & ~127;
}

__global__ void rminit_kernel() { g_rowmap[blockIdx.x * 256 + threadIdx.x] = -1; }
__global__ void rmfill_kernel() {
    int b = blockIdx.x, k = threadIdx.x;
    if (k < g_n[b]) g_rowmap[g_off[b] + k] = (b << 6) | k;
}

__global__ __launch_bounds__(128)
void outfill_kernel(float* __restrict__ out, float* __restrict__ outb)
{
    int r = blockIdx.x;
    int b = r >> 6, k = r & 63;
    int n = g_n[b];
    if (outb && threadIdx.x == 0) outb[r] = (k < n) ? (float)b : -1.0f;
    if (k >= n)
        ((float4*)(out + (size_t)r * DDIM))[threadIdx.x] = make_float4(0.f, 0.f, 0.f, 0.f);
}

// =====================================================================
// GEMM1 (fp16 HMMA + ldmatrix): g_Th = half(mish( (zc*key) @ W1 + b1 ))
// CTA 128m x 256n, 512 thr, K chunk 32 halves, rows stride 20 words (80B)
// =====================================================================
#define G1_AW   128
#define G1_B0W  2688
#define G1_B1W  7808
#define G1_B0B  10752u
#define G1_B1B  31232u
#define G1_BYTES 51712

__global__ void __launch_bounds__(512, 1)
gemm1_kernel(const float* __restrict__ key, const float* __restrict__ b1)
{
    const int tile = blockIdx.x;
    if (tile * 128 >= g_vpad) return;
    extern __shared__ uint32_t smw[];
    int* rm_s = (int*)smw;
    char* smb = (char*)smw;
    const uint32_t sb = smem_u32(smw);

    const int tid = threadIdx.x, lane = tid & 31, wid = tid >> 5;
    const int mw = wid & 3, nw = wid >> 2;
    const int nc0 = blockIdx.y * 256;

    if (tid < 128) rm_s[tid] = g_rowmap[tile * 128 + tid];
    __syncthreads();

    const float* zp[2]; const float* kp[2]; uint32_t adst[2];
#pragma unroll
    for (int i = 0; i < 2; i++) {
        int idx = tid + i * 512;
        int r = idx >> 3, seg = idx & 7;
        int rm = rm_s[r]; if (rm < 0) rm = 0;
        zp[i] = g_zc + (size_t)(rm >> 6) * HDIM + seg * 4;
        kp[i] = key + (size_t)(rm & 63) * HDIM + seg * 4;
        adst[i] = 512u + (uint32_t)r * 80u + (uint32_t)seg * 8u;
    }
    const __half* bsrc[2]; uint32_t boff[2];
#pragma unroll
    for (int i = 0; i < 2; i++) {
        int idx = tid + i * 512;
        int r = idx >> 2, seg = idx & 3;
        bsrc[i] = g_W1Th + (size_t)(nc0 + r) * HDIM + seg * 8;
        boff[i] = (uint32_t)r * 80u + (uint32_t)seg * 16u;
    }

    // ldmatrix per-lane offsets (words, excluding buffer base and ks)
    const int lr = lane & 7, grp = lane >> 3;
    uint32_t aoffW[2], boffW[4];
#pragma unroll
    for (int mt = 0; mt < 2; mt++)
        aoffW[mt] = G1_AW + (uint32_t)(mw * 32 + mt * 16 + lr + (grp & 1) * 8) * 20u + (uint32_t)(grp >> 1) * 4u;
#pragma unroll
    for (int p = 0; p < 4; p++)
        boffW[p] = (uint32_t)(nw * 64 + p * 16 + lr + (grp >> 1) * 8) * 20u + (uint32_t)(grp & 1) * 4u;

    float4 za[2], ka[2];
#pragma unroll
    for (int i = 0; i < 2; i++) { za[i] = *(const float4*)zp[i]; ka[i] = *(const float4*)kp[i]; }
#pragma unroll
    for (int i = 0; i < 2; i++)
        CPASYNC16(sb + G1_B0B + boff[i], (const char*)bsrc[i]);
    CPCOMMIT();

    float acc[2][8][4];
#pragma unroll
    for (int mt = 0; mt < 2; mt++)
#pragma unroll
        for (int nt = 0; nt < 8; nt++)
#pragma unroll
            for (int q = 0; q < 4; q++) acc[mt][nt][q] = 0.f;

    for (int kt = 0; kt < 32; kt++) {
        const int buf = kt & 1;
#pragma unroll
        for (int i = 0; i < 2; i++) {
            float4 p;
            p.x = za[i].x * ka[i].x; p.y = za[i].y * ka[i].y;
            p.z = za[i].z * ka[i].z; p.w = za[i].w * ka[i].w;
            uint2 v;
            v.x = h2u(__floats2half2_rn(p.x, p.y));
            v.y = h2u(__floats2half2_rn(p.z, p.w));
            *(uint2*)(smb + adst[i]) = v;
        }
        if (kt + 1 < 32) {
#pragma unroll
            for (int i = 0; i < 2; i++) {
                za[i] = *(const float4*)(zp[i] + (kt + 1) * 32);
                ka[i] = *(const float4*)(kp[i] + (kt + 1) * 32);
            }
            const uint32_t bbB = ((kt + 1) & 1) ? G1_B1B : G1_B0B;
#pragma unroll
            for (int i = 0; i < 2; i++)
                CPASYNC16(sb + bbB + boff[i], (const char*)(bsrc[i] + (kt + 1) * 32));
            CPCOMMIT();
            CPWAIT1();
        } else {
            CPWAIT0();
        }
        __syncthreads();

        const uint32_t bw = buf ? G1_B1W : G1_B0W;
#pragma unroll
        for (int ks = 0; ks < 2; ks++) {
            uint32_t af[2][4];
            ldsm4(af[0], sb + (aoffW[0] + ks * 8) * 4);
            ldsm4(af[1], sb + (aoffW[1] + ks * 8) * 4);
#pragma unroll
            for (int p = 0; p < 4; p++) {
                uint32_t bfr[4];
                ldsm4(bfr, sb + (bw + boffW[p] + ks * 8) * 4);
                mma_f16(acc[0][2 * p], af[0], bfr);
                mma_f16(acc[1][2 * p], af[1], bfr);
                mma_f16(acc[0][2 * p + 1], af[0], bfr + 2);
                mma_f16(acc[1][2 * p + 1], af[1], bfr + 2);
            }
        }
        __syncthreads();
    }

    const int col00 = nc0 + nw * 64 + 2 * (lane & 3);
    const int row00 = tile * 128 + mw * 32 + (lane >> 2);
#pragma unroll
    for (int mt = 0; mt < 2; mt++) {
#pragma unroll
        for (int nt = 0; nt < 8; nt++) {
            int col = col00 + nt * 8;
            float2 bb = *(const float2*)(b1 + col);
            __half2 v0 = __floats2half2_rn(mish_poly(acc[mt][nt][0] + bb.x),
                                           mish_poly(acc[mt][nt][1] + bb.y));
            __half2 v1 = __floats2half2_rn(mish_poly(acc[mt][nt][2] + bb.x),
                                           mish_poly(acc[mt][nt][3] + bb.y));
            *(__half2*)(g_Th + (size_t)(row00 + mt * 16) * MID_DEC + col) = v0;
            *(__half2*)(g_Th + (size_t)(row00 + mt * 16 + 8) * MID_DEC + col) = v1;
        }
    }
}

// =====================================================================
// GEMM2 (fp16 HMMA + ldmatrix): out = g_Th @ W2 + b2, scatter by rowmap
// =====================================================================
#define G2_A0W  128
#define G2_A1W  2688
#define G2_B0W  5248
#define G2_B1W  10368
#define G2_A0B  512u
#define G2_A1B  10752u
#define G2_B0B  20992u
#define G2_B1B  41472u
#define G2_BYTES 61952

__global__ void __launch_bounds__(512, 1)
gemm2_kernel(const float* __restrict__ b2, float* __restrict__ out)
{
    const int tile = blockIdx.x;
    if (tile * 128 >= g_vpad) return;
    extern __shared__ uint32_t smw[];
    int* rm_s = (int*)smw;
    const uint32_t sb = smem_u32(smw);

    const int tid = threadIdx.x, lane = tid & 31, wid = tid >> 5;
    const int mw = wid & 3, nw = wid >> 2;
    const int nc0 = blockIdx.y * 256;

    if (tid < 128) rm_s[tid] = g_rowmap[tile * 128 + tid];

    const __half* asrc = g_Th + (size_t)(tile * 128 + (tid >> 2)) * MID_DEC + (tid & 3) * 8;
    const uint32_t aoff = (uint32_t)(tid >> 2) * 80u + (uint32_t)(tid & 3) * 16u;
    const __half* bsrc[2]; uint32_t boff[2];
#pragma unroll
    for (int i = 0; i < 2; i++) {
        int idx = tid + i * 512;
        int r = idx >> 2, seg = idx & 3;
        bsrc[i] = g_W2Th + (size_t)(nc0 + r) * MID_DEC + seg * 8;
        boff[i] = (uint32_t)r * 80u + (uint32_t)seg * 16u;
    }

    const int lr = lane & 7, grp = lane >> 3;
    uint32_t aoffW[2], boffW[4];
#pragma unroll
    for (int mt = 0; mt < 2; mt++)
        aoffW[mt] = (uint32_t)(mw * 32 + mt * 16 + lr + (grp & 1) * 8) * 20u + (uint32_t)(grp >> 1) * 4u;
#pragma unroll
    for (int p = 0; p < 4; p++)
        boffW[p] = (uint32_t)(nw * 64 + p * 16 + lr + (grp >> 1) * 8) * 20u + (uint32_t)(grp & 1) * 4u;

    CPASYNC16(sb + G2_A0B + aoff, (const char*)asrc);
#pragma unroll
    for (int i = 0; i < 2; i++)
        CPASYNC16(sb + G2_B0B + boff[i], (const char*)bsrc[i]);
    CPCOMMIT();

    float acc[2][8][4];
#pragma unroll
    for (int mt = 0; mt < 2; mt++)
#pragma unroll
        for (int nt = 0; nt < 8; nt++)
#pragma unroll
            for (int q = 0; q < 4; q++) acc[mt][nt][q] = 0.f;

    for (int kt = 0; kt < 24; kt++) {
        const int buf = kt & 1;
        if (kt + 1 < 24) {
            const int nb = (kt + 1) & 1;
            CPASYNC16(sb + (nb ? G2_A1B : G2_A0B) + aoff, (const char*)(asrc + (kt + 1) * 32));
#pragma unroll
            for (int i = 0; i < 2; i++)
                CPASYNC16(sb + (nb ? G2_B1B : G2_B0B) + boff[i], (const char*)(bsrc[i] + (kt + 1) * 32));
            CPCOMMIT();
            CPWAIT1();
        } else {
            CPWAIT0();
        }
        __syncthreads();

        const uint32_t aw = buf ? G2_A1W : G2_A0W;
        const uint32_t bw = buf ? G2_B1W : G2_B0W;
#pragma unroll
        for (int ks = 0; ks < 2; ks++) {
            uint32_t af[2][4];
            ldsm4(af[0], sb + (aw + aoffW[0] + ks * 8) * 4);
            ldsm4(af[1], sb + (aw + aoffW[1] + ks * 8) * 4);
#pragma unroll
            for (int p = 0; p < 4; p++) {
                uint32_t bfr[4];
                ldsm4(bfr, sb + (bw + boffW[p] + ks * 8) * 4);
                mma_f16(acc[0][2 * p], af[0], bfr);
                mma_f16(acc[1][2 * p], af[1], bfr);
                mma_f16(acc[0][2 * p + 1], af[0], bfr + 2);
                mma_f16(acc[1][2 * p + 1], af[1], bfr + 2);
            }
        }
        __syncthreads();
    }

    const int col00 = nc0 + nw * 64 + 2 * (lane & 3);
    const int mrow0 = mw * 32 + (lane >> 2);
#pragma unroll
    for (int mt = 0; mt < 2; mt++) {
        int r0 = mrow0 + mt * 16;
        int rm0 = rm_s[r0];
        int rm1 = rm_s[r0 + 8];
#pragma unroll
        for (int nt = 0; nt < 8; nt++) {
            int col = col00 + nt * 8;
            float2 bb = *(const float2*)(b2 + col);
            if (rm0 >= 0) {
                float2 v; v.x = acc[mt][nt][0] + bb.x; v.y = acc[mt][nt][1] + bb.y;
                *(float2*)(out + (size_t)rm0 * DDIM + col) = v;
            }
            if (rm1 >= 0) {
                float2 v; v.x = acc[mt][nt][2] + bb.x; v.y = acc[mt][nt][3] + bb.y;
                *(float2*)(out + (size_t)rm1 * DDIM + col) = v;
            }
        }
    }
}

extern "C" void kernel_launch(void* const* d_in, const int* in_sizes, int n_in,
                              void* d_out, int out_size)
{
    const float* z      = (const float*)d_in[0];
    const float* key    = (const float*)d_in[1];
    const float* sp_w1  = (const float*)d_in[2];
    const float* sp_b1  = (const float*)d_in[3];
    const float* sp_g   = (const float*)d_in[4];
    const float* sp_bt  = (const float*)d_in[5];
    const float* sp_w2  = (const float*)d_in[6];
    const float* sp_b2  = (const float*)d_in[7];
    const float* cd_w1  = (const float*)d_in[8];
    const float* cd_b1  = (const float*)d_in[9];
    const float* cd_w2  = (const float*)d_in[10];
    const float* cd_b2  = (const float*)d_in[11];
    const float* dec_w1 = (const float*)d_in[12];
    const float* dec_b1 = (const float*)d_in[13];
    const float* dec_w2 = (const float*)d_in[14];
    const float* dec_b2 = (const float*)d_in[15];
    float* out = (float*)d_out;

    const int sp_smem = (16 * HDIM + 48) * 4;
    cudaFuncSetAttribute(size_pred_kernel, cudaFuncAttributeMaxDynamicSharedMemorySize, sp_smem);
    cudaFuncSetAttribute(gemm1_kernel, cudaFuncAttributeMaxDynamicSharedMemorySize, G1_BYTES);
    cudaFuncSetAttribute(gemm2_kernel, cudaFuncAttributeMaxDynamicSharedMemorySize, G2_BYTES);

    size_pred_kernel<<<B_SZ / 16, 256, sp_smem>>>(z, sp_w1, sp_b1, sp_g, sp_bt, sp_w2, sp_b2);
    enc_kernel<<<65, 256>>>(cd_w1, cd_b1, cd_w2, cd_b2);
    zc_kernel<<<(B_SZ * HDIM) / 256, 256>>>(z);
    dim3 tb(32, 8);
    transpose_h<<<dim3(MID_DEC / 32, HDIM / 32), tb>>>(dec_w1, HDIM, MID_DEC, 0);
    transpose_h<<<dim3(DDIM / 32, MID_DEC / 32), tb>>>(dec_w2, MID_DEC, DDIM, 1);
    scan_kernel<<<1, 1024>>>();
    rminit_kernel<<<NROWS / 256, 256>>>();
    rmfill_kernel<<<B_SZ, MAXN>>>();

    gemm1_kernel<<<dim3(NROWS / 128, 3), 512, G1_BYTES>>>(key, dec_b1);
    gemm2_kernel<<<dim3(NROWS / 128, 2), 512, G2_BYTES>>>(dec_b2, out);

    long long x_elems = (long long)B_SZ * MAXN * DDIM;
    float* outb = ((long long)out_size >= x_elems + (long long)NROWS) ? (out + x_elems) : (float*)0;
    outfill_kernel<<<NROWS, 128>>>(out, outb);
}